// round 13
// baseline (speedup 1.0000x reference)
#include <cuda_runtime.h>
#include <cstdint>

// ---------------------------------------------------------------------------
// TimeMix collapses to: out = (sigmoid(xr @ Wr^T) * (xv @ Wv^T or wkv@t0)) @ Wo^T
// For t>0 padded state is zero so wkv == v; the 4 t==0 rows use a side buffer
// g_wkv0 computed directly from raw inputs (fp32 dot products).
// Engine: legacy mma.sync tf32 (tcgen05 unusable: harness targets compute_103).
// R12: GEMM0+GEMM1 merged into one 2048-CTA launch with per-tile release/
//      acquire flags -> saves ~1 tail CTA-round; t0 fix decoupled from g_v.
// ---------------------------------------------------------------------------

namespace {
constexpr int  BDIM = 4;
constexpr int  TDIM = 2048;
constexpr int  CDIM = 2048;
constexpr long MDIM = (long)BDIM * TDIM;   // 8192
constexpr int  KDIM = CDIM;
constexpr int  NDIM = CDIM;

constexpr int BM = 128, BN = 128, BK = 32;
constexpr int NTHREADS = 128;
constexpr int LSTR = 36;                           // padded row stride (floats)
constexpr int MATA_FLOATS  = BM * LSTR;            // 4608
constexpr int MATB_FLOATS  = BN * LSTR;            // 4608
constexpr int STAGE_FLOATS = MATA_FLOATS + MATB_FLOATS;   // 9216
constexpr int NSTAGE = 3;
constexpr int DYN_SMEM = NSTAGE * STAGE_FLOATS * 4;       // 110592
constexpr int NKT = KDIM / BK;                     // 64
constexpr int MTILES = 64, NTILES = 16;
}

// Scratch (static device arrays — no cudaMalloc anywhere)
__device__ float g_xv[MDIM * KDIM];
__device__ float g_xr[MDIM * KDIM];
__device__ float g_v [MDIM * NDIM];
__device__ float g_rv[MDIM * NDIM];
__device__ float g_wv[(long)NDIM * KDIM];
__device__ float g_wr[(long)NDIM * KDIM];
__device__ float g_wo[(long)NDIM * KDIM];
__device__ float g_wkv0[(long)BDIM * NDIM];        // wkv for the 4 t=0 rows
__device__ int   g_flags[MTILES * NTILES];         // mode0 -> mode1 tile flags

__device__ __forceinline__ float rna_tf32(float f) {
    uint32_t u;
    asm("cvt.rna.tf32.f32 %0, %1;" : "=r"(u) : "f"(f));
    return __uint_as_float(u);
}
__device__ __forceinline__ void cp16(uint32_t s, const void* g) {
    asm volatile("cp.async.cg.shared.global [%0], [%1], 16;" :: "r"(s), "l"(g));
}

// ---- round live weights to tf32; block 0 also resets the tile flags
__global__ void prep_w_kernel(const float* __restrict__ wv,
                              const float* __restrict__ wr,
                              const float* __restrict__ wo) {
    if (blockIdx.x == 0) {
        for (int j = threadIdx.x; j < MTILES * NTILES; j += blockDim.x)
            g_flags[j] = 0;
    }
    long i = ((long)blockIdx.x * blockDim.x + threadIdx.x) * 4;
    float4 a = *(const float4*)(wv + i);
    float4 b = *(const float4*)(wr + i);
    float4 c = *(const float4*)(wo + i);
    a.x = rna_tf32(a.x); a.y = rna_tf32(a.y); a.z = rna_tf32(a.z); a.w = rna_tf32(a.w);
    b.x = rna_tf32(b.x); b.y = rna_tf32(b.y); b.z = rna_tf32(b.z); b.w = rna_tf32(b.w);
    c.x = rna_tf32(c.x); c.y = rna_tf32(c.y); c.z = rna_tf32(c.z); c.w = rna_tf32(c.w);
    *(float4*)(g_wv + i) = a;
    *(float4*)(g_wr + i) = b;
    *(float4*)(g_wo + i) = c;
}

// ---- token-mix + tf32 rounding for the two GEMM A-operands
__global__ void prep_x_kernel(const float* __restrict__ x,
                              const float* __restrict__ tmv,
                              const float* __restrict__ tmr,
                              const float* __restrict__ xxp) {
    long i = ((long)blockIdx.x * blockDim.x + threadIdx.x) * 4;
    int  c = (int)(i & (CDIM - 1));
    float4 xv = *(const float4*)(x   + i);
    float4 mv = *(const float4*)(tmv + c);
    float4 mr = *(const float4*)(tmr + c);
    float4 xc = *(const float4*)(xxp + c);
    float4 ov, orr;
    ov.x  = rna_tf32(xv.x * mv.x + (1.f - mv.x) * xc.x);
    ov.y  = rna_tf32(xv.y * mv.y + (1.f - mv.y) * xc.y);
    ov.z  = rna_tf32(xv.z * mv.z + (1.f - mv.z) * xc.z);
    ov.w  = rna_tf32(xv.w * mv.w + (1.f - mv.w) * xc.w);
    orr.x = rna_tf32(xv.x * mr.x + (1.f - mr.x) * xc.x);
    orr.y = rna_tf32(xv.y * mr.y + (1.f - mr.y) * xc.y);
    orr.z = rna_tf32(xv.z * mr.z + (1.f - mr.z) * xc.z);
    orr.w = rna_tf32(xv.w * mr.w + (1.f - mr.w) * xc.w);
    *(float4*)(g_xv + i) = ov;
    *(float4*)(g_xr + i) = orr;
}

// ---- t==0 rows: compute k and v dot products (fp32) from raw inputs, then wkv.
// Independent of the GEMMs; feeds mode1 epilogue via g_wkv0.
__global__ void t0_wkv_kernel(const float* __restrict__ x,
                              const float* __restrict__ tf,
                              const float* __restrict__ tmk,
                              const float* __restrict__ tmv,
                              const float* __restrict__ xxp,
                              const float* __restrict__ aa,
                              const float* __restrict__ bb,
                              const float* __restrict__ pp,
                              const float* __restrict__ wk,
                              const float* __restrict__ wv) {
    const int b    = blockIdx.y;
    const int o    = blockIdx.x * 8 + (threadIdx.x >> 5);
    const int lane = threadIdx.x & 31;
    const float* xrow = x  + (long)b * TDIM * CDIM;  // x[b][0][:]
    const float* wkr  = wk + (long)o * CDIM;
    const float* wvr  = wv + (long)o * CDIM;
    float sk = 0.f, sv = 0.f;
    for (int c = lane; c < CDIM; c += 32) {
        float xc = xrow[c], mx = xxp[c];
        float mk = tmk[c], mv = tmv[c];
        sk += (xc * mk + (1.f - mk) * mx) * wkr[c];
        sv += (xc * mv + (1.f - mv) * mx) * wvr[c];
    }
    #pragma unroll
    for (int off = 16; off; off >>= 1) {
        sk += __shfl_xor_sync(0xffffffffu, sk, off);
        sv += __shfl_xor_sync(0xffffffffu, sv, off);
    }
    if (lane == 0) {
        float ww = tf[o] + sk;
        float p  = pp[o];
        float qq = fmaxf(p, ww);
        float e1 = expf(p  - qq);
        float e2 = expf(ww - qq);
        g_wkv0[(long)b * NDIM + o] = (e1 * aa[o] + e2 * sv) / (e1 * bb[o] + e2);
    }
}

// ---- shared GEMM mainloop body (CTA 128x128, 4 warps, 3-stage cp.async,
//      register-fragment double buffering). acc must be zeroed by caller.
#define GEMM_MAINLOOP(A, W, bm, bn)                                              \
    const uint32_t sbase = (uint32_t)__cvta_generic_to_shared(sm);               \
    const int srow = tid >> 3;                                                   \
    const int scol = (tid & 7) * 4;                                              \
    const float* gA = (A) + ((bm) + srow) * (long)KDIM + scol;                   \
    const float* gB = (W) + ((bn) + srow) * (long)KDIM + scol;                   \
    const uint32_t dOff = (uint32_t)(srow * LSTR + scol) * 4u;                   \
    LOAD_STAGE(0, 0);                                                            \
    LOAD_STAGE(1, 1);                                                            \
    float a[2][4][4], b[2][8][2];                                                \
    for (int kt = 0; kt < NKT; ++kt) {                                           \
        asm volatile("cp.async.wait_group 1;" ::: "memory");                     \
        __syncthreads();                                                         \
        const float* As_ = sm + (kt % NSTAGE) * STAGE_FLOATS;                    \
        const float* Bs_ = As_ + MATA_FLOATS;                                    \
        LOAD_FRAGS(a[0], b[0], As_, Bs_, 0);                                     \
        const int jt = kt + 2;                                                   \
        if (jt < NKT) { LOAD_STAGE(jt % NSTAGE, jt); }                           \
        else          { asm volatile("cp.async.commit_group;"); }                \
        _Pragma("unroll")                                                        \
        for (int ks = 0; ks < 4; ks++) {                                         \
            const int cur = ks & 1, nxt = cur ^ 1;                               \
            if (ks < 3) LOAD_FRAGS(a[nxt], b[nxt], As_, Bs_, ks + 1);            \
            _Pragma("unroll")                                                    \
            for (int im = 0; im < 4; im++)                                       \
                _Pragma("unroll")                                                \
                for (int in = 0; in < 8; in++)                                   \
                    asm volatile(                                                \
                        "mma.sync.aligned.m16n8k8.row.col.f32.tf32.tf32.f32 "    \
                        "{%0,%1,%2,%3}, {%4,%5,%6,%7}, {%8,%9}, {%0,%1,%2,%3};"  \
                        : "+f"(acc[im][in][0]), "+f"(acc[im][in][1]),            \
                          "+f"(acc[im][in][2]), "+f"(acc[im][in][3])             \
                        : "r"(__float_as_uint(a[cur][im][0])), "r"(__float_as_uint(a[cur][im][1])), \
                          "r"(__float_as_uint(a[cur][im][2])), "r"(__float_as_uint(a[cur][im][3])), \
                          "r"(__float_as_uint(b[cur][in][0])), "r"(__float_as_uint(b[cur][in][1]))); \
        }                                                                        \
    }

#define LOAD_STAGE(s, kt) do {                                                   \
    uint32_t _a = sbase + (uint32_t)(s) * (STAGE_FLOATS * 4) + dOff;             \
    uint32_t _b = _a + (uint32_t)(MATA_FLOATS * 4);                              \
    int _k = (kt) * BK;                                                          \
    _Pragma("unroll")                                                            \
    for (int _i = 0; _i < 8; _i++) {                                             \
        cp16(_a + (uint32_t)(_i * 16 * LSTR * 4), gA + (long)(_i * 16) * KDIM + _k); \
        cp16(_b + (uint32_t)(_i * 16 * LSTR * 4), gB + (long)(_i * 16) * KDIM + _k); \
    }                                                                            \
    asm volatile("cp.async.commit_group;");                                      \
} while (0)

#define LOAD_FRAGS(fa, fb, As_, Bs_, ks) do {                                    \
    _Pragma("unroll")                                                            \
    for (int _im = 0; _im < 4; _im++) {                                          \
        const float* _p = (As_) + (wm * 64 + _im * 16 + g) * LSTR + (ks) * 8 + t;\
        (fa)[_im][0] = _p[0];                                                    \
        (fa)[_im][1] = _p[8 * LSTR];                                             \
        (fa)[_im][2] = _p[4];                                                    \
        (fa)[_im][3] = _p[8 * LSTR + 4];                                         \
    }                                                                            \
    _Pragma("unroll")                                                            \
    for (int _in = 0; _in < 8; _in++) {                                          \
        const float* _p = (Bs_) + (wn * 64 + _in * 8 + g) * LSTR + (ks) * 8 + t; \
        (fb)[_in][0] = _p[0];                                                    \
        (fb)[_in][1] = _p[4];                                                    \
    }                                                                            \
} while (0)

// ---- merged GEMM0+GEMM1: grid (16, 128).
// y in [0,64):  mode0  g_v  = g_xv @ g_wv^T   (+ release flag per tile)
// y in [64,128): mode1 g_rv = rna(sigmoid(g_xr @ g_wr^T) * v)   (acquire flag)
__global__ void __launch_bounds__(NTHREADS, 2)
gemm01_kernel() {
    extern __shared__ float sm[];
    const bool isR = (blockIdx.y >= 64);
    const int  ty  = blockIdx.y & 63;
    const int  tileid = ty * NTILES + blockIdx.x;

    const float* __restrict__ A = isR ? g_xr : g_xv;
    const float* __restrict__ W = isR ? g_wr : g_wv;

    const int tid  = threadIdx.x;
    const int lane = tid & 31;
    const int warp = tid >> 5;
    const int wm = warp & 1;
    const int wn = warp >> 1;
    const int g  = lane >> 2;
    const int t  = lane & 3;
    const long bm = (long)ty * BM;
    const long bn = (long)blockIdx.x * BN;

    float acc[4][8][4];
    #pragma unroll
    for (int i = 0; i < 4; i++)
        #pragma unroll
        for (int j = 0; j < 8; j++)
            #pragma unroll
            for (int k = 0; k < 4; k++) acc[i][j][k] = 0.f;

    GEMM_MAINLOOP(A, W, bm, bn)

    if (!isR) {
        // mode0 epilogue: store v, then release the tile flag
        #pragma unroll
        for (int im = 0; im < 4; im++) {
            const long m0 = bm + wm * 64 + im * 16 + g;
            #pragma unroll
            for (int in = 0; in < 8; in++) {
                const long n0 = bn + wn * 64 + in * 8 + t * 2;
                const long i0 = m0 * NDIM + n0;
                const long i1 = i0 + 8L * NDIM;
                *(float2*)(g_v + i0) = make_float2(acc[im][in][0], acc[im][in][1]);
                *(float2*)(g_v + i1) = make_float2(acc[im][in][2], acc[im][in][3]);
            }
        }
        __threadfence();
        __syncthreads();
        if (tid == 0) atomicExch(&g_flags[tileid], 1);
    } else {
        // mode1 epilogue: acquire the matching mode0 tile, then fuse
        if (tid == 0) { while (atomicAdd(&g_flags[tileid], 0) == 0) { } }
        __syncthreads();
        __threadfence();
        #pragma unroll
        for (int im = 0; im < 4; im++) {
            const long m0 = bm + wm * 64 + im * 16 + g;
            const bool t0row = ((m0 & (TDIM - 1)) == 0);
            #pragma unroll
            for (int in = 0; in < 8; in++) {
                const long n0 = bn + wn * 64 + in * 8 + t * 2;
                const long i0 = m0 * NDIM + n0;
                const long i1 = i0 + 8L * NDIM;
                const float2* vp0 = t0row
                    ? (const float2*)(g_wkv0 + (m0 >> 11) * (long)NDIM + n0)
                    : (const float2*)(g_v + i0);
                float2 v0 = __ldcg(vp0);
                float2 v1 = __ldcg((const float2*)(g_v + i1));
                float r0 = 1.f / (1.f + __expf(-acc[im][in][0]));
                float r1 = 1.f / (1.f + __expf(-acc[im][in][1]));
                float r2 = 1.f / (1.f + __expf(-acc[im][in][2]));
                float r3 = 1.f / (1.f + __expf(-acc[im][in][3]));
                *(float2*)(g_rv + i0) = make_float2(rna_tf32(r0 * v0.x), rna_tf32(r1 * v0.y));
                *(float2*)(g_rv + i1) = make_float2(rna_tf32(r2 * v1.x), rna_tf32(r3 * v1.y));
            }
        }
    }
}

// ---- final GEMM: out = g_rv @ g_wo^T
__global__ void __launch_bounds__(NTHREADS, 2)
gemm2_kernel(float* __restrict__ Cout) {
    extern __shared__ float sm[];
    const int tid  = threadIdx.x;
    const int lane = tid & 31;
    const int warp = tid >> 5;
    const int wm = warp & 1;
    const int wn = warp >> 1;
    const int g  = lane >> 2;
    const int t  = lane & 3;
    const long bm = (long)blockIdx.y * BM;
    const long bn = (long)blockIdx.x * BN;

    float acc[4][8][4];
    #pragma unroll
    for (int i = 0; i < 4; i++)
        #pragma unroll
        for (int j = 0; j < 8; j++)
            #pragma unroll
            for (int k = 0; k < 4; k++) acc[i][j][k] = 0.f;

    GEMM_MAINLOOP(g_rv, g_wo, bm, bn)

    #pragma unroll
    for (int im = 0; im < 4; im++) {
        const long m0 = bm + wm * 64 + im * 16 + g;
        #pragma unroll
        for (int in = 0; in < 8; in++) {
            const long n0 = bn + wn * 64 + in * 8 + t * 2;
            const long i0 = m0 * NDIM + n0;
            const long i1 = i0 + 8L * NDIM;
            *(float2*)(Cout + i0) = make_float2(acc[im][in][0], acc[im][in][1]);
            *(float2*)(Cout + i1) = make_float2(acc[im][in][2], acc[im][in][3]);
        }
    }
}

extern "C" void kernel_launch(void* const* d_in, const int* in_sizes, int n_in,
                              void* d_out, int out_size) {
    (void)in_sizes; (void)n_in; (void)out_size;
    const float* x   = (const float*)d_in[0];
    const float* tf  = (const float*)d_in[1];
    const float* tmk = (const float*)d_in[2];
    const float* tmv = (const float*)d_in[3];
    const float* tmr = (const float*)d_in[4];
    const float* xxp = (const float*)d_in[5];
    const float* aa  = (const float*)d_in[6];
    const float* bb  = (const float*)d_in[7];
    const float* pp  = (const float*)d_in[8];
    const float* wk  = (const float*)d_in[9];
    const float* wv  = (const float*)d_in[10];
    const float* wr  = (const float*)d_in[11];
    const float* wo  = (const float*)d_in[12];
    float* out = (float*)d_out;

    static bool attr_done = false;
    if (!attr_done) {
        cudaFuncSetAttribute(gemm01_kernel, cudaFuncAttributeMaxDynamicSharedMemorySize, DYN_SMEM);
        cudaFuncSetAttribute(gemm2_kernel,  cudaFuncAttributeMaxDynamicSharedMemorySize, DYN_SMEM);
        attr_done = true;
    }

    prep_w_kernel<<<(unsigned)(((long)NDIM * KDIM) / 1024), 256>>>(wv, wr, wo);
    prep_x_kernel<<<(unsigned)((MDIM * (long)KDIM) / 1024), 256>>>(x, tmv, tmr, xxp);
    t0_wkv_kernel<<<dim3(CDIM / 8, BDIM), 256>>>(x, tf, tmk, tmv, xxp, aa, bb, pp, wk, wv);

    gemm01_kernel<<<dim3(NTILES, 2 * MTILES), NTHREADS, DYN_SMEM>>>();
    gemm2_kernel<<<dim3(NTILES, MTILES), NTHREADS, DYN_SMEM>>>(out);
}

// round 14
// speedup vs baseline: 1.8679x; 1.8679x over previous
#include <cuda_runtime.h>
#include <cuda_fp16.h>
#include <cstdint>

// ---------------------------------------------------------------------------
// TimeMix collapses to: out = (sigmoid(xr @ Wr^T) * (xv @ Wv^T or wkv@t0)) @ Wo^T
// For t>0 padded state is zero so wkv == v; only 4 rows at t==0 need wkv.
// Engine: legacy mma.sync (tcgen05 unusable: harness targets compute_103).
// R13: tf32 k8 -> fp16 k16 MMA. Same 10-bit mantissa => same accuracy; 2x K
// per MMA, half the smem/DRAM bytes per FLOP, half the barriers (BK=64).
// ---------------------------------------------------------------------------

namespace {
constexpr int  BDIM = 4;
constexpr int  TDIM = 2048;
constexpr int  CDIM = 2048;
constexpr long MDIM = (long)BDIM * TDIM;   // 8192
constexpr int  KDIM = CDIM;
constexpr int  NDIM = CDIM;

constexpr int BM = 128, BN = 128, BK = 64;
constexpr int NTHREADS = 128;
constexpr int LSTR_H = 72;                          // padded row stride (halves) = 144B
constexpr int MATA_HALFS  = BM * LSTR_H;            // 9216 halves = 18432 B
constexpr int STAGE_HALFS = 2 * MATA_HALFS;         // A + B
constexpr int MATA_BYTES  = MATA_HALFS * 2;
constexpr int STAGE_BYTES = STAGE_HALFS * 2;        // 36864
constexpr int NSTAGE = 3;
constexpr int DYN_SMEM = NSTAGE * STAGE_BYTES;      // 110592
constexpr int NKT = KDIM / BK;                      // 32
}

// Scratch (static device arrays — no cudaMalloc anywhere)
__device__ __half g_xv[MDIM * KDIM];
__device__ __half g_xr[MDIM * KDIM];
__device__ __half g_rv[MDIM * NDIM];
__device__ __half g_wv[(long)NDIM * KDIM];
__device__ __half g_wr[(long)NDIM * KDIM];
__device__ __half g_wo[(long)NDIM * KDIM];
__device__ float  g_v [MDIM * NDIM];

__device__ __forceinline__ void cp16(uint32_t s, const void* g) {
    asm volatile("cp.async.cg.shared.global [%0], [%1], 16;" :: "r"(s), "l"(g));
}

// ---- convert the three live weight matrices to fp16 (RN)
__global__ void prep_w_kernel(const float* __restrict__ wv,
                              const float* __restrict__ wr,
                              const float* __restrict__ wo) {
    long i = ((long)blockIdx.x * blockDim.x + threadIdx.x) * 4;
    float4 a = *(const float4*)(wv + i);
    float4 b = *(const float4*)(wr + i);
    float4 c = *(const float4*)(wo + i);
    __half2* pv = reinterpret_cast<__half2*>(g_wv + i);
    __half2* pr = reinterpret_cast<__half2*>(g_wr + i);
    __half2* po = reinterpret_cast<__half2*>(g_wo + i);
    pv[0] = __floats2half2_rn(a.x, a.y); pv[1] = __floats2half2_rn(a.z, a.w);
    pr[0] = __floats2half2_rn(b.x, b.y); pr[1] = __floats2half2_rn(b.z, b.w);
    po[0] = __floats2half2_rn(c.x, c.y); po[1] = __floats2half2_rn(c.z, c.w);
}

// ---- token-mix (fp32) + fp16 conversion for the two GEMM A-operands
__global__ void prep_x_kernel(const float* __restrict__ x,
                              const float* __restrict__ tmv,
                              const float* __restrict__ tmr,
                              const float* __restrict__ xxp) {
    long i = ((long)blockIdx.x * blockDim.x + threadIdx.x) * 4;
    int  c = (int)(i & (CDIM - 1));
    float4 xv = *(const float4*)(x   + i);
    float4 mv = *(const float4*)(tmv + c);
    float4 mr = *(const float4*)(tmr + c);
    float4 xc = *(const float4*)(xxp + c);
    float vx = xv.x * mv.x + (1.f - mv.x) * xc.x;
    float vy = xv.y * mv.y + (1.f - mv.y) * xc.y;
    float vz = xv.z * mv.z + (1.f - mv.z) * xc.z;
    float vw = xv.w * mv.w + (1.f - mv.w) * xc.w;
    float rx = xv.x * mr.x + (1.f - mr.x) * xc.x;
    float ry = xv.y * mr.y + (1.f - mr.y) * xc.y;
    float rz = xv.z * mr.z + (1.f - mr.z) * xc.z;
    float rw = xv.w * mr.w + (1.f - mr.w) * xc.w;
    __half2* pv = reinterpret_cast<__half2*>(g_xv + i);
    __half2* pr = reinterpret_cast<__half2*>(g_xr + i);
    pv[0] = __floats2half2_rn(vx, vy); pv[1] = __floats2half2_rn(vz, vw);
    pr[0] = __floats2half2_rn(rx, ry); pr[1] = __floats2half2_rn(rz, rw);
}

// ---- t==0 correction: full wkv for the 4 t=0 rows, overwrite g_v (fp32 dot).
__global__ void t0_fix_kernel(const float* __restrict__ x,
                              const float* __restrict__ tf,
                              const float* __restrict__ tmk,
                              const float* __restrict__ xxp,
                              const float* __restrict__ aa,
                              const float* __restrict__ bb,
                              const float* __restrict__ pp,
                              const float* __restrict__ wk) {
    const int b    = blockIdx.y;
    const int o    = blockIdx.x * 8 + (threadIdx.x >> 5);
    const int lane = threadIdx.x & 31;
    const float* xrow = x  + (long)b * TDIM * CDIM;
    const float* wrow = wk + (long)o * CDIM;
    float s = 0.f;
    for (int c = lane; c < CDIM; c += 32) {
        float xk = xrow[c] * tmk[c] + (1.f - tmk[c]) * xxp[c];
        s += xk * wrow[c];
    }
    #pragma unroll
    for (int off = 16; off; off >>= 1) s += __shfl_xor_sync(0xffffffffu, s, off);
    if (lane == 0) {
        float ww = tf[o] + s;
        float p  = pp[o];
        float qq = fmaxf(p, ww);
        float e1 = expf(p  - qq);
        float e2 = expf(ww - qq);
        long idx = (long)b * TDIM * NDIM + o;
        float v  = g_v[idx];
        g_v[idx] = (e1 * aa[o] + e2 * v) / (e1 * bb[o] + e2);
    }
}

// ---- fp16 mma.sync GEMM:  C[M,N] = A[M,K] @ W[N,K]^T, CTA 128x128, 4 warps,
//      warp tile 64x64, BK=64 (4 x k16 steps), 3-stage cp.async,
//      register-fragment double buffering.
// MODE 0: g_v  = g_xv @ g_wv^T                      (fp32 out)
// MODE 1: g_rv = half( sigmoid(g_xr @ g_wr^T) * g_v )
// MODE 2: out  = g_rv @ g_wo^T                      (fp32 out)
template<int MODE>
__global__ void __launch_bounds__(NTHREADS, 2)
gemm_f16(float* __restrict__ Cout) {
    const __half* __restrict__ A = (MODE == 0) ? g_xv : (MODE == 1) ? g_xr : g_rv;
    const __half* __restrict__ W = (MODE == 0) ? g_wv : (MODE == 1) ? g_wr : g_wo;

    extern __shared__ __half smh[];   // [3 stages][A 128x72h | B 128x72h]

    const int tid  = threadIdx.x;
    const int lane = tid & 31;
    const int warp = tid >> 5;
    const int wm = warp & 1;          // 2 warps over M (64 rows each)
    const int wn = warp >> 1;         // 2 warps over N (64 cols each)
    const int g  = lane >> 2;
    const int t  = lane & 3;
    const long bm = (long)blockIdx.y * BM;
    const long bn = (long)blockIdx.x * BN;

    float acc[4][8][4];
    #pragma unroll
    for (int i = 0; i < 4; i++)
        #pragma unroll
        for (int j = 0; j < 8; j++)
            #pragma unroll
            for (int k = 0; k < 4; k++) acc[i][j][k] = 0.f;

    const uint32_t sbase = (uint32_t)__cvta_generic_to_shared(smh);

    // cp.async: per stage A = 128 rows x 8 chunks(16B) = 1024 -> 8/thread; B same.
    const int srow = tid >> 3;            // 0..15
    const int schk = (tid & 7) * 8;       // half offset of 16B chunk
    const __half* gA = A + (bm + srow) * (long)KDIM + schk;
    const __half* gB = W + (bn + srow) * (long)KDIM + schk;
    const uint32_t dOff = (uint32_t)(srow * LSTR_H + schk) * 2u;

    #define LOAD_STAGE(s, kt) do {                                               \
        uint32_t _a = sbase + (uint32_t)(s) * STAGE_BYTES + dOff;                \
        uint32_t _b = _a + (uint32_t)MATA_BYTES;                                 \
        int _k = (kt) * BK;                                                      \
        _Pragma("unroll")                                                        \
        for (int _i = 0; _i < 8; _i++) {                                         \
            cp16(_a + (uint32_t)(_i * 16 * LSTR_H * 2), gA + (long)(_i * 16) * KDIM + _k); \
            cp16(_b + (uint32_t)(_i * 16 * LSTR_H * 2), gB + (long)(_i * 16) * KDIM + _k); \
        }                                                                        \
        asm volatile("cp.async.commit_group;");                                  \
    } while (0)

    // Fragment load for one k16 step into buffers fa/fb (packed half2 in u32)
    #define LOAD_FRAGS(fa, fb, As_, Bs_, ks) do {                                \
        _Pragma("unroll")                                                        \
        for (int _im = 0; _im < 4; _im++) {                                      \
            const __half* _p = (As_) + (wm * 64 + _im * 16 + g) * LSTR_H + (ks) * 16 + 2 * t; \
            (fa)[_im][0] = *(const uint32_t*)(_p);                               \
            (fa)[_im][1] = *(const uint32_t*)(_p + 8 * LSTR_H);                  \
            (fa)[_im][2] = *(const uint32_t*)(_p + 8);                           \
            (fa)[_im][3] = *(const uint32_t*)(_p + 8 * LSTR_H + 8);              \
        }                                                                        \
        _Pragma("unroll")                                                        \
        for (int _in = 0; _in < 8; _in++) {                                      \
            const __half* _p = (Bs_) + (wn * 64 + _in * 8 + g) * LSTR_H + (ks) * 16 + 2 * t; \
            (fb)[_in][0] = *(const uint32_t*)(_p);                               \
            (fb)[_in][1] = *(const uint32_t*)(_p + 8);                           \
        }                                                                        \
    } while (0)

    LOAD_STAGE(0, 0);
    LOAD_STAGE(1, 1);

    uint32_t a[2][4][4], b[2][8][2];

    for (int kt = 0; kt < NKT; ++kt) {
        asm volatile("cp.async.wait_group 1;" ::: "memory");
        __syncthreads();
        const __half* As_ = smh + (kt % NSTAGE) * STAGE_HALFS;
        const __half* Bs_ = As_ + MATA_HALFS;
        LOAD_FRAGS(a[0], b[0], As_, Bs_, 0);          // prime ks=0 fragments
        const int jt = kt + 2;
        if (jt < NKT) { LOAD_STAGE(jt % NSTAGE, jt); }
        else          { asm volatile("cp.async.commit_group;"); }
        #pragma unroll
        for (int ks = 0; ks < 4; ks++) {
            const int cur = ks & 1, nxt = cur ^ 1;
            if (ks < 3) LOAD_FRAGS(a[nxt], b[nxt], As_, Bs_, ks + 1);
            #pragma unroll
            for (int im = 0; im < 4; im++)
                #pragma unroll
                for (int in = 0; in < 8; in++)
                    asm volatile(
                        "mma.sync.aligned.m16n8k16.row.col.f32.f16.f16.f32 "
                        "{%0,%1,%2,%3}, {%4,%5,%6,%7}, {%8,%9}, {%0,%1,%2,%3};"
                        : "+f"(acc[im][in][0]), "+f"(acc[im][in][1]),
                          "+f"(acc[im][in][2]), "+f"(acc[im][in][3])
                        : "r"(a[cur][im][0]), "r"(a[cur][im][1]),
                          "r"(a[cur][im][2]), "r"(a[cur][im][3]),
                          "r"(b[cur][in][0]), "r"(b[cur][in][1]));
        }
    }
    #undef LOAD_STAGE
    #undef LOAD_FRAGS

    // Epilogue: c0,c1 = (row m0, cols n0,n0+1); c2,c3 = row m0+8.
    #pragma unroll
    for (int im = 0; im < 4; im++) {
        const long m0 = bm + wm * 64 + im * 16 + g;
        #pragma unroll
        for (int in = 0; in < 8; in++) {
            const long n0 = bn + wn * 64 + in * 8 + t * 2;
            const long i0 = m0 * NDIM + n0;
            const long i1 = i0 + 8L * NDIM;
            float c0 = acc[im][in][0], c1 = acc[im][in][1];
            float c2 = acc[im][in][2], c3 = acc[im][in][3];
            if (MODE == 0) {
                *(float2*)(g_v + i0) = make_float2(c0, c1);
                *(float2*)(g_v + i1) = make_float2(c2, c3);
            } else if (MODE == 1) {
                float2 v0 = *(const float2*)(g_v + i0);
                float2 v1 = *(const float2*)(g_v + i1);
                float r0 = 1.f / (1.f + __expf(-c0));
                float r1 = 1.f / (1.f + __expf(-c1));
                float r2 = 1.f / (1.f + __expf(-c2));
                float r3 = 1.f / (1.f + __expf(-c3));
                *(__half2*)(g_rv + i0) = __floats2half2_rn(r0 * v0.x, r1 * v0.y);
                *(__half2*)(g_rv + i1) = __floats2half2_rn(r2 * v1.x, r3 * v1.y);
            } else {
                *(float2*)(Cout + i0) = make_float2(c0, c1);
                *(float2*)(Cout + i1) = make_float2(c2, c3);
            }
        }
    }
}

extern "C" void kernel_launch(void* const* d_in, const int* in_sizes, int n_in,
                              void* d_out, int out_size) {
    (void)in_sizes; (void)n_in; (void)out_size;
    const float* x   = (const float*)d_in[0];
    const float* tf  = (const float*)d_in[1];
    const float* tmk = (const float*)d_in[2];
    const float* tmv = (const float*)d_in[3];
    const float* tmr = (const float*)d_in[4];
    const float* xxp = (const float*)d_in[5];
    const float* aa  = (const float*)d_in[6];
    const float* bb  = (const float*)d_in[7];
    const float* pp  = (const float*)d_in[8];
    const float* wk  = (const float*)d_in[9];
    const float* wv  = (const float*)d_in[10];
    const float* wr  = (const float*)d_in[11];
    const float* wo  = (const float*)d_in[12];
    float* out = (float*)d_out;

    static bool attr_done = false;
    if (!attr_done) {
        cudaFuncSetAttribute(gemm_f16<0>, cudaFuncAttributeMaxDynamicSharedMemorySize, DYN_SMEM);
        cudaFuncSetAttribute(gemm_f16<1>, cudaFuncAttributeMaxDynamicSharedMemorySize, DYN_SMEM);
        cudaFuncSetAttribute(gemm_f16<2>, cudaFuncAttributeMaxDynamicSharedMemorySize, DYN_SMEM);
        attr_done = true;
    }

    prep_w_kernel<<<(unsigned)(((long)NDIM * KDIM) / 1024), 256>>>(wv, wr, wo);
    prep_x_kernel<<<(unsigned)((MDIM * (long)KDIM) / 1024), 256>>>(x, tmv, tmr, xxp);

    dim3 grid((unsigned)(NDIM / BN), (unsigned)(MDIM / BM));   // (16, 64)
    gemm_f16<0><<<grid, NTHREADS, DYN_SMEM>>>(nullptr);        // g_v = xv @ Wv^T
    t0_fix_kernel<<<dim3(CDIM / 8, BDIM), 256>>>(x, tf, tmk, xxp, aa, bb, pp, wk);
    gemm_f16<1><<<grid, NTHREADS, DYN_SMEM>>>(nullptr);        // g_rv = sig(xr@Wr^T)*g_v
    gemm_f16<2><<<grid, NTHREADS, DYN_SMEM>>>(out);            // out = g_rv @ Wo^T
}